// round 9
// baseline (speedup 1.0000x reference)
#include <cuda_runtime.h>

#define SEQ    4096
#define BATCH  16
#define HIDDEN 512
#define SPC    16                    // s per chunk
#define CPB    (SEQ / SPC)           // 256 chunks per batch
#define SLOTS  37                    // persistent slots per batch
#define NPART  (SLOTS * 2)           // 74 ctx partials per (b,h)
#define CTXN   (BATCH * HIDDEN)      // 8192

// Scratch (no allocations allowed) — all fully re-written every launch.
__device__ float g_dec[BATCH * HIDDEN];              // decoder features [b][h]
__device__ float g_w[BATCH * SEQ];                   // unnormalized masked weights
__device__ float g_zpart[BATCH * SLOTS];             // per-(b,slot) Z partials
__device__ float g_part[BATCH * NPART * HIDDEN];     // ctx partials [b][slot*2+par][h]

__device__ __forceinline__ float tanh_fast(float x) {
    float y;
    asm("tanh.approx.f32 %0, %1;" : "=f"(y) : "f"(x));
    return y;
}

// ---------------------------------------------------------------------------
// K0: decoder_features[b,k] = dot(x[b,:], W[k,:]) + bias[k].
// Grid 1024 = 16 b * 64 k-groups of 8. Block 256 (8 warps), ONE row per warp.
// No smem, no barrier.
// ---------------------------------------------------------------------------
__global__ void k0_dec(const float* __restrict__ x, const float* __restrict__ W,
                       const float* __restrict__ bias) {
    int b    = blockIdx.x >> 6;
    int kg   = blockIdx.x & 63;
    int tid  = threadIdx.x;               // 256
    int warp = tid >> 5, lane = tid & 31;
    int k = kg * 8 + warp;

    const float4* Wr = reinterpret_cast<const float4*>(W + (size_t)k * HIDDEN);
    const float4* xr = reinterpret_cast<const float4*>(x + (size_t)b * HIDDEN);

    float4 wv[4], xv[4];
#pragma unroll
    for (int j = 0; j < 4; ++j) wv[j] = Wr[lane + j * 32];
#pragma unroll
    for (int j = 0; j < 4; ++j) xv[j] = __ldg(&xr[lane + j * 32]);

    float acc = 0.0f;
#pragma unroll
    for (int j = 0; j < 4; ++j) {
        acc += wv[j].x * xv[j].x + wv[j].y * xv[j].y
             + wv[j].z * xv[j].z + wv[j].w * xv[j].w;
    }
#pragma unroll
    for (int off = 16; off; off >>= 1) acc += __shfl_down_sync(0xffffffffu, acc, off);
    if (lane == 0) g_dec[b * HIDDEN + k] = acc + bias[k];
}

// ---------------------------------------------------------------------------
// KMAIN: persistent fused scores+context. Round-7 structure, but ws is
// DOUBLE-BUFFERED so each chunk needs only ONE __syncthreads().
// Safety: a warp writes buffer p^1 only after passing the next chunk's sync,
// which cannot happen while any warp still reads buffer p (it would be
// blocked at that same sync).
// Grid 592 = 16 b * 37 slots, block 256 (8 warps).
// ---------------------------------------------------------------------------
__global__ void __launch_bounds__(256)
kmain(const float* __restrict__ encf, const float* __restrict__ enc,
      const float* __restrict__ mask, const float* __restrict__ tss,
      const float* __restrict__ v,    float* __restrict__ out_newsum) {
    int b    = blockIdx.x / SLOTS;
    int slot = blockIdx.x % SLOTS;
    int tid  = threadIdx.x;               // 256
    int warp = tid >> 5, lane = tid & 31;

    __shared__ float ws[2][SPC];
    __shared__ float zs[8];

    // Register cache of decoder features + v for this thread's 16 h-positions.
    const float4* dsg = reinterpret_cast<const float4*>(g_dec + b * HIDDEN);
    const float4* vsg = reinterpret_cast<const float4*>(v);
    float4 ds4[4], vs4[4];
#pragma unroll
    for (int j = 0; j < 4; ++j) {
        ds4[j] = dsg[lane + j * 32];
        vs4[j] = vsg[lane + j * 32];
    }

    // Phase-B persistent state.
    int par = tid >> 7;                   // 0/1
    int h4  = tid & 127;
    const size_t strideS = (size_t)BATCH * (HIDDEN / 4);     // float4s per s-step
    const float4* enc4 = reinterpret_cast<const float4*>(enc);
    float4 ctx = make_float4(0.f, 0.f, 0.f, 0.f);
    float zacc = 0.0f;
    int buf = 0;

    for (int c = slot; c < CPB; c += SLOTS) {
        int sbase = c * SPC;
        int s0 = sbase + warp * 2;

        // ---- Phase A: 2 rows per warp ----
        float4 ev[2][4];
#pragma unroll
        for (int i = 0; i < 2; ++i) {
            const float4* row =
                reinterpret_cast<const float4*>(encf + ((size_t)(s0 + i) * BATCH + b) * HIDDEN);
#pragma unroll
            for (int j = 0; j < 4; ++j) ev[i][j] = row[lane + j * 32];
        }
        float acc[2] = {0.f, 0.f};
#pragma unroll
        for (int i = 0; i < 2; ++i) {
#pragma unroll
            for (int j = 0; j < 4; ++j) {
                acc[i] += tanh_fast(ds4[j].x + ev[i][j].x) * vs4[j].x;
                acc[i] += tanh_fast(ds4[j].y + ev[i][j].y) * vs4[j].y;
                acc[i] += tanh_fast(ds4[j].z + ev[i][j].z) * vs4[j].z;
                acc[i] += tanh_fast(ds4[j].w + ev[i][j].w) * vs4[j].w;
            }
        }
#pragma unroll
        for (int i = 0; i < 2; ++i) {
#pragma unroll
            for (int off = 16; off; off >>= 1)
                acc[i] += __shfl_down_sync(0xffffffffu, acc[i], off);
            if (lane == 0) {
                int s = s0 + i;
                float e = expf(acc[i]);
                float t = tss[b * SEQ + s];
                float w = mask[b * SEQ + s] * e / t;
                out_newsum[b * SEQ + s] = e + t;
                g_w[b * SEQ + s] = w;
                ws[buf][warp * 2 + i] = w;
                zacc += w;
            }
        }
        __syncthreads();   // the ONLY barrier per chunk

        // ---- Phase B: accumulate ctx for this chunk ----
        const float4* p = enc4 + ((size_t)(sbase + par) * BATCH + b) * (HIDDEN / 4) + h4;
#pragma unroll
        for (int i = 0; i < SPC / 2; ++i) {
            float  wv = ws[buf][2 * i + par];
            float4 e  = __ldg(p + (size_t)(2 * i) * strideS);
            ctx.x += wv * e.x; ctx.y += wv * e.y; ctx.z += wv * e.z; ctx.w += wv * e.w;
        }
        buf ^= 1;
    }

    // Write one ctx partial per thread.
    reinterpret_cast<float4*>(g_part)
        [((size_t)b * NPART + slot * 2 + par) * (HIDDEN / 4) + h4] = ctx;

    // Deterministic Z partial for this (b, slot).
    if (lane == 0) zs[warp] = zacc;
    __syncthreads();
    if (tid == 0) {
        float z = 0.0f;
#pragma unroll
        for (int i = 0; i < 8; ++i) z += zs[i];
        g_zpart[b * SLOTS + slot] = z;
    }
}

// ---------------------------------------------------------------------------
// K4 (fused epilogue): blocks 0..31: ctx = (sum of 74 partials)/Z -> out[0:8192)
//                      blocks 32..287: attention = w/Z -> out[8192:73728)
// ---------------------------------------------------------------------------
__global__ void k4_final(float* __restrict__ out) {
    int bid = blockIdx.x, tid = threadIdx.x;
    if (bid < 32) {
        int i = bid * 256 + tid;            // 0..8191
        int b = i >> 9;
        float Z = 0.0f;
#pragma unroll
        for (int j = 0; j < SLOTS; ++j) Z += g_zpart[b * SLOTS + j];
        float acc = 0.0f;
        int h = i & (HIDDEN - 1);
#pragma unroll 8
        for (int p = 0; p < NPART; ++p)
            acc += g_part[((size_t)b * NPART + p) * HIDDEN + h];
        out[i] = acc / Z;
    } else {
        int i = (bid - 32) * 256 + tid;     // 0..65535
        int b = i >> 12;
        float Z = 0.0f;
#pragma unroll
        for (int j = 0; j < SLOTS; ++j) Z += g_zpart[b * SLOTS + j];
        out[CTXN + i] = g_w[i] / Z;
    }
}

// ---------------------------------------------------------------------------
extern "C" void kernel_launch(void* const* d_in, const int* in_sizes, int n_in,
                              void* d_out, int out_size) {
    const float* x    = (const float*)d_in[0];  // outputs_hidden [1,16,512]
    const float* enc  = (const float*)d_in[1];  // encoder_out [4096,16,512]
    const float* encf = (const float*)d_in[2];  // encoder_features [4096,16,512]
    const float* mask = (const float*)d_in[3];  // encoder_mask [16,1,4096]
    const float* tss  = (const float*)d_in[4];  // temporal_scores_sum [16,1,4096]
    const float* W    = (const float*)d_in[5];  // W_feat [512,512]
    const float* bias = (const float*)d_in[6];  // b_feat [512]
    const float* v    = (const float*)d_in[7];  // v_attn [512]

    float* out        = (float*)d_out;
    float* out_newsum = out + CTXN + BATCH * SEQ;  // third output

    k0_dec  <<<1024,          256>>>(x, W, bias);
    kmain   <<<BATCH * SLOTS, 256>>>(encf, enc, mask, tss, v, out_newsum);
    k4_final<<<288,           256>>>(out);
}

// round 10
// speedup vs baseline: 1.5034x; 1.5034x over previous
#include <cuda_runtime.h>

#define SEQ    4096
#define BATCH  16
#define HIDDEN 512
#define SPC    16                    // s per chunk
#define CPB    (SEQ / SPC)           // 256 chunks per batch
#define SLOTS  37                    // persistent slots per batch
#define NPART  (SLOTS * 2)           // 74 ctx partials per (b,h)
#define CTXN   (BATCH * HIDDEN)      // 8192

// Scratch (no allocations allowed) — all fully re-written every launch.
__device__ float g_dec[BATCH * HIDDEN];              // decoder features [b][h]
__device__ float g_w[BATCH * SEQ];                   // unnormalized masked weights
__device__ float g_zpart[BATCH * SLOTS];             // per-(b,slot) Z partials
__device__ float g_part[BATCH * NPART * HIDDEN];     // ctx partials [b][slot*2+par][h]

__device__ __forceinline__ float tanh_fast(float x) {
    float y;
    asm("tanh.approx.f32 %0, %1;" : "=f"(y) : "f"(x));
    return y;
}

// ---------------------------------------------------------------------------
// K0: decoder_features[b,k] = dot(x[b,:], W[k,:]) + bias[k].
// Grid 1024 = 16 b * 64 k-groups of 8. Block 256 (8 warps), ONE row per warp.
// ---------------------------------------------------------------------------
__global__ void k0_dec(const float* __restrict__ x, const float* __restrict__ W,
                       const float* __restrict__ bias) {
    int b    = blockIdx.x >> 6;
    int kg   = blockIdx.x & 63;
    int tid  = threadIdx.x;               // 256
    int warp = tid >> 5, lane = tid & 31;
    int k = kg * 8 + warp;

    const float4* Wr = reinterpret_cast<const float4*>(W + (size_t)k * HIDDEN);
    const float4* xr = reinterpret_cast<const float4*>(x + (size_t)b * HIDDEN);

    float4 wv[4], xv[4];
#pragma unroll
    for (int j = 0; j < 4; ++j) wv[j] = Wr[lane + j * 32];
#pragma unroll
    for (int j = 0; j < 4; ++j) xv[j] = __ldg(&xr[lane + j * 32]);

    float acc = 0.0f;
#pragma unroll
    for (int j = 0; j < 4; ++j) {
        acc += wv[j].x * xv[j].x + wv[j].y * xv[j].y
             + wv[j].z * xv[j].z + wv[j].w * xv[j].w;
    }
#pragma unroll
    for (int off = 16; off; off >>= 1) acc += __shfl_down_sync(0xffffffffu, acc, off);
    if (lane == 0) g_dec[b * HIDDEN + k] = acc + bias[k];
}

// ---------------------------------------------------------------------------
// KMAIN: persistent fused scores+context — round-7 structure verbatim
// (two barriers per chunk), EXCEPT ds/vs live in shared memory (LDS.128,
// conflict-free) instead of 32 registers, and occupancy is forced to
// 5 blocks/SM. Grid 592 = 16 b * 37 slots, block 256 (8 warps).
// ---------------------------------------------------------------------------
__global__ void __launch_bounds__(256, 5)
kmain(const float* __restrict__ encf, const float* __restrict__ enc,
      const float* __restrict__ mask, const float* __restrict__ tss,
      const float* __restrict__ v,    float* __restrict__ out_newsum) {
    int b    = blockIdx.x / SLOTS;
    int slot = blockIdx.x % SLOTS;
    int tid  = threadIdx.x;               // 256
    int warp = tid >> 5, lane = tid & 31;

    __shared__ float4 ds_s[HIDDEN / 4];   // 128 float4
    __shared__ float4 vs_s[HIDDEN / 4];
    __shared__ float  ws[SPC];
    __shared__ float  zs[8];

    // Stage decoder features + v into shared (once per block).
    if (tid < 128) ds_s[tid] = reinterpret_cast<const float4*>(g_dec + b * HIDDEN)[tid];
    else           vs_s[tid - 128] = reinterpret_cast<const float4*>(v)[tid - 128];
    __syncthreads();

    // Phase-B persistent state.
    int par = tid >> 7;                   // 0/1
    int h4  = tid & 127;
    const size_t strideS = (size_t)BATCH * (HIDDEN / 4);     // float4s per s-step
    const float4* enc4 = reinterpret_cast<const float4*>(enc);
    float4 ctx = make_float4(0.f, 0.f, 0.f, 0.f);
    float zacc = 0.0f;

    for (int c = slot; c < CPB; c += SLOTS) {
        int sbase = c * SPC;
        int s0 = sbase + warp * 2;

        // ---- Phase A: 2 rows per warp ----
        float4 ev[2][4];
#pragma unroll
        for (int i = 0; i < 2; ++i) {
            const float4* row =
                reinterpret_cast<const float4*>(encf + ((size_t)(s0 + i) * BATCH + b) * HIDDEN);
#pragma unroll
            for (int j = 0; j < 4; ++j) ev[i][j] = row[lane + j * 32];
        }
        float acc[2] = {0.f, 0.f};
#pragma unroll
        for (int j = 0; j < 4; ++j) {
            float4 d4 = ds_s[lane + j * 32];     // LDS.128, conflict-free
            float4 v4 = vs_s[lane + j * 32];
#pragma unroll
            for (int i = 0; i < 2; ++i) {
                acc[i] += tanh_fast(d4.x + ev[i][j].x) * v4.x;
                acc[i] += tanh_fast(d4.y + ev[i][j].y) * v4.y;
                acc[i] += tanh_fast(d4.z + ev[i][j].z) * v4.z;
                acc[i] += tanh_fast(d4.w + ev[i][j].w) * v4.w;
            }
        }
#pragma unroll
        for (int i = 0; i < 2; ++i) {
#pragma unroll
            for (int off = 16; off; off >>= 1)
                acc[i] += __shfl_down_sync(0xffffffffu, acc[i], off);
            if (lane == 0) {
                int s = s0 + i;
                float e = expf(acc[i]);
                float t = tss[b * SEQ + s];
                float w = mask[b * SEQ + s] * e / t;
                out_newsum[b * SEQ + s] = e + t;
                g_w[b * SEQ + s] = w;
                ws[warp * 2 + i] = w;
                zacc += w;
            }
        }
        __syncthreads();

        // ---- Phase B: accumulate ctx for this chunk ----
        const float4* p = enc4 + ((size_t)(sbase + par) * BATCH + b) * (HIDDEN / 4) + h4;
#pragma unroll
        for (int i = 0; i < SPC / 2; ++i) {
            float  wv = ws[2 * i + par];
            float4 e  = __ldg(p + (size_t)(2 * i) * strideS);
            ctx.x += wv * e.x; ctx.y += wv * e.y; ctx.z += wv * e.z; ctx.w += wv * e.w;
        }
        __syncthreads();   // keep warps phase-aligned (proven necessary in R9)
    }

    // Write one ctx partial per thread.
    reinterpret_cast<float4*>(g_part)
        [((size_t)b * NPART + slot * 2 + par) * (HIDDEN / 4) + h4] = ctx;

    // Deterministic Z partial for this (b, slot).
    if (lane == 0) zs[warp] = zacc;
    __syncthreads();
    if (tid == 0) {
        float z = 0.0f;
#pragma unroll
        for (int i = 0; i < 8; ++i) z += zs[i];
        g_zpart[b * SLOTS + slot] = z;
    }
}

// ---------------------------------------------------------------------------
// K4 (fused epilogue): blocks 0..31: ctx = (sum of 74 partials)/Z -> out[0:8192)
//                      blocks 32..287: attention = w/Z -> out[8192:73728)
// ---------------------------------------------------------------------------
__global__ void k4_final(float* __restrict__ out) {
    int bid = blockIdx.x, tid = threadIdx.x;
    if (bid < 32) {
        int i = bid * 256 + tid;            // 0..8191
        int b = i >> 9;
        float Z = 0.0f;
#pragma unroll
        for (int j = 0; j < SLOTS; ++j) Z += g_zpart[b * SLOTS + j];
        float acc = 0.0f;
        int h = i & (HIDDEN - 1);
#pragma unroll 8
        for (int p = 0; p < NPART; ++p)
            acc += g_part[((size_t)b * NPART + p) * HIDDEN + h];
        out[i] = acc / Z;
    } else {
        int i = (bid - 32) * 256 + tid;     // 0..65535
        int b = i >> 12;
        float Z = 0.0f;
#pragma unroll
        for (int j = 0; j < SLOTS; ++j) Z += g_zpart[b * SLOTS + j];
        out[CTXN + i] = g_w[i] / Z;
    }
}

// ---------------------------------------------------------------------------
extern "C" void kernel_launch(void* const* d_in, const int* in_sizes, int n_in,
                              void* d_out, int out_size) {
    const float* x    = (const float*)d_in[0];  // outputs_hidden [1,16,512]
    const float* enc  = (const float*)d_in[1];  // encoder_out [4096,16,512]
    const float* encf = (const float*)d_in[2];  // encoder_features [4096,16,512]
    const float* mask = (const float*)d_in[3];  // encoder_mask [16,1,4096]
    const float* tss  = (const float*)d_in[4];  // temporal_scores_sum [16,1,4096]
    const float* W    = (const float*)d_in[5];  // W_feat [512,512]
    const float* bias = (const float*)d_in[6];  // b_feat [512]
    const float* v    = (const float*)d_in[7];  // v_attn [512]

    float* out        = (float*)d_out;
    float* out_newsum = out + CTXN + BATCH * SEQ;  // third output

    k0_dec  <<<1024,          256>>>(x, W, bias);
    kmain   <<<BATCH * SLOTS, 256>>>(encf, enc, mask, tss, v, out_newsum);
    k4_final<<<288,           256>>>(out);
}

// round 11
// speedup vs baseline: 1.6152x; 1.0744x over previous
#include <cuda_runtime.h>

#define SEQ    4096
#define BATCH  16
#define HIDDEN 512
#define SPC    16                    // s per chunk
#define CPB    (SEQ / SPC)           // 256 chunks per batch
#define SLOTS  37                    // persistent slots per batch
#define CTXN   (BATCH * HIDDEN)      // 8192

// Scratch (no allocations allowed) — all fully re-written every launch.
__device__ float g_dec[BATCH * HIDDEN];              // decoder features [b][h]
__device__ float g_w[BATCH * SEQ];                   // unnormalized masked weights
__device__ float g_zpart[BATCH * SLOTS];             // per-(b,slot) Z partials
__device__ float g_part[BATCH * SLOTS * HIDDEN];     // ctx partials [b][slot][h]

__device__ __forceinline__ float tanh_fast(float x) {
    float y;
    asm("tanh.approx.f32 %0, %1;" : "=f"(y) : "f"(x));
    return y;
}

// ---------------------------------------------------------------------------
// K0: decoder_features[b,k] = dot(x[b,:], W[k,:]) + bias[k].
// Grid 512 = 16 b * 32 k-groups of 16. Block 256 (8 warps), TWO rows per warp
// (8 independent W LDG.128 per thread in flight; single wave).
// ---------------------------------------------------------------------------
__global__ void k0_dec(const float* __restrict__ x, const float* __restrict__ W,
                       const float* __restrict__ bias) {
    int b    = blockIdx.x >> 5;
    int kg   = blockIdx.x & 31;
    int tid  = threadIdx.x;               // 256
    int warp = tid >> 5, lane = tid & 31;
    int k0 = kg * 16 + warp * 2;

    const float4* xr = reinterpret_cast<const float4*>(x + (size_t)b * HIDDEN);
    float4 xv[4];
#pragma unroll
    for (int j = 0; j < 4; ++j) xv[j] = __ldg(&xr[lane + j * 32]);

    float4 wv[2][4];
#pragma unroll
    for (int r = 0; r < 2; ++r) {
        const float4* Wr = reinterpret_cast<const float4*>(W + (size_t)(k0 + r) * HIDDEN);
#pragma unroll
        for (int j = 0; j < 4; ++j) wv[r][j] = Wr[lane + j * 32];
    }

    float acc[2] = {0.f, 0.f};
#pragma unroll
    for (int r = 0; r < 2; ++r)
#pragma unroll
        for (int j = 0; j < 4; ++j)
            acc[r] += wv[r][j].x * xv[j].x + wv[r][j].y * xv[j].y
                    + wv[r][j].z * xv[j].z + wv[r][j].w * xv[j].w;

#pragma unroll
    for (int r = 0; r < 2; ++r) {
#pragma unroll
        for (int off = 16; off; off >>= 1)
            acc[r] += __shfl_down_sync(0xffffffffu, acc[r], off);
        if (lane == 0) g_dec[b * HIDDEN + k0 + r] = acc[r] + bias[k0 + r];
    }
}

// ---------------------------------------------------------------------------
// KMAIN: persistent fused scores+context — proven round-10 structure
// (two barriers per chunk, smem ds/vs, 5 blocks/SM), plus an end-of-kernel
// parity reduce so only ONE ctx partial per (b,slot,h) is written.
// Grid 592 = 16 b * 37 slots, block 256 (8 warps).
// ---------------------------------------------------------------------------
__global__ void __launch_bounds__(256, 5)
kmain(const float* __restrict__ encf, const float* __restrict__ enc,
      const float* __restrict__ mask, const float* __restrict__ tss,
      const float* __restrict__ v,    float* __restrict__ out_newsum) {
    int b    = blockIdx.x / SLOTS;
    int slot = blockIdx.x % SLOTS;
    int tid  = threadIdx.x;               // 256
    int warp = tid >> 5, lane = tid & 31;

    __shared__ float4 ds_s[HIDDEN / 4];   // 128 float4
    __shared__ float4 vs_s[HIDDEN / 4];
    __shared__ float4 red_s[HIDDEN / 4];  // parity-reduce staging
    __shared__ float  ws[SPC];
    __shared__ float  zs[8];

    // Stage decoder features + v into shared (once per block).
    if (tid < 128) ds_s[tid] = reinterpret_cast<const float4*>(g_dec + b * HIDDEN)[tid];
    else           vs_s[tid - 128] = reinterpret_cast<const float4*>(v)[tid - 128];
    __syncthreads();

    // Phase-B persistent state.
    int par = tid >> 7;                   // 0/1
    int h4  = tid & 127;
    const size_t strideS = (size_t)BATCH * (HIDDEN / 4);     // float4s per s-step
    const float4* enc4 = reinterpret_cast<const float4*>(enc);
    float4 ctx = make_float4(0.f, 0.f, 0.f, 0.f);
    float zacc = 0.0f;

    for (int c = slot; c < CPB; c += SLOTS) {
        int sbase = c * SPC;
        int s0 = sbase + warp * 2;

        // ---- Phase A: 2 rows per warp ----
        float4 ev[2][4];
#pragma unroll
        for (int i = 0; i < 2; ++i) {
            const float4* row =
                reinterpret_cast<const float4*>(encf + ((size_t)(s0 + i) * BATCH + b) * HIDDEN);
#pragma unroll
            for (int j = 0; j < 4; ++j) ev[i][j] = row[lane + j * 32];
        }
        float acc[2] = {0.f, 0.f};
#pragma unroll
        for (int j = 0; j < 4; ++j) {
            float4 d4 = ds_s[lane + j * 32];     // LDS.128, conflict-free
            float4 v4 = vs_s[lane + j * 32];
#pragma unroll
            for (int i = 0; i < 2; ++i) {
                acc[i] += tanh_fast(d4.x + ev[i][j].x) * v4.x;
                acc[i] += tanh_fast(d4.y + ev[i][j].y) * v4.y;
                acc[i] += tanh_fast(d4.z + ev[i][j].z) * v4.z;
                acc[i] += tanh_fast(d4.w + ev[i][j].w) * v4.w;
            }
        }
#pragma unroll
        for (int i = 0; i < 2; ++i) {
#pragma unroll
            for (int off = 16; off; off >>= 1)
                acc[i] += __shfl_down_sync(0xffffffffu, acc[i], off);
            if (lane == 0) {
                int s = s0 + i;
                float e = expf(acc[i]);
                float t = tss[b * SEQ + s];
                float w = mask[b * SEQ + s] * e / t;
                out_newsum[b * SEQ + s] = e + t;
                g_w[b * SEQ + s] = w;
                ws[warp * 2 + i] = w;
                zacc += w;
            }
        }
        __syncthreads();

        // ---- Phase B: accumulate ctx for this chunk ----
        const float4* p = enc4 + ((size_t)(sbase + par) * BATCH + b) * (HIDDEN / 4) + h4;
#pragma unroll
        for (int i = 0; i < SPC / 2; ++i) {
            float  wv = ws[2 * i + par];
            float4 e  = __ldg(p + (size_t)(2 * i) * strideS);
            ctx.x += wv * e.x; ctx.y += wv * e.y; ctx.z += wv * e.z; ctx.w += wv * e.w;
        }
        __syncthreads();   // keep warps phase-aligned (proven necessary in R9)
    }

    // ---- Parity reduce: one ctx partial per (b,slot,h) ----
    if (par == 1) red_s[h4] = ctx;
    __syncthreads();
    if (par == 0) {
        float4 o = red_s[h4];
        ctx.x += o.x; ctx.y += o.y; ctx.z += o.z; ctx.w += o.w;
        reinterpret_cast<float4*>(g_part)
            [((size_t)b * SLOTS + slot) * (HIDDEN / 4) + h4] = ctx;
    }

    // Deterministic Z partial for this (b, slot).
    if (lane == 0) zs[warp] = zacc;
    __syncthreads();
    if (tid == 0) {
        float z = 0.0f;
#pragma unroll
        for (int i = 0; i < 8; ++i) z += zs[i];
        g_zpart[b * SLOTS + slot] = z;
    }
}

// ---------------------------------------------------------------------------
// K4 (fused epilogue): blocks 0..31: ctx = (sum of 37 partials)/Z -> out[0:8192)
//                      blocks 32..287: attention = w/Z -> out[8192:73728)
// ---------------------------------------------------------------------------
__global__ void k4_final(float* __restrict__ out) {
    int bid = blockIdx.x, tid = threadIdx.x;
    if (bid < 32) {
        int i = bid * 256 + tid;            // 0..8191
        int b = i >> 9;
        float Z = 0.0f;
#pragma unroll
        for (int j = 0; j < SLOTS; ++j) Z += g_zpart[b * SLOTS + j];
        float acc = 0.0f;
        int h = i & (HIDDEN - 1);
#pragma unroll
        for (int p = 0; p < SLOTS; ++p)
            acc += g_part[((size_t)b * SLOTS + p) * HIDDEN + h];
        out[i] = acc / Z;
    } else {
        int i = (bid - 32) * 256 + tid;     // 0..65535
        int b = i >> 12;
        float Z = 0.0f;
#pragma unroll
        for (int j = 0; j < SLOTS; ++j) Z += g_zpart[b * SLOTS + j];
        out[CTXN + i] = g_w[i] / Z;
    }
}

// ---------------------------------------------------------------------------
extern "C" void kernel_launch(void* const* d_in, const int* in_sizes, int n_in,
                              void* d_out, int out_size) {
    const float* x    = (const float*)d_in[0];  // outputs_hidden [1,16,512]
    const float* enc  = (const float*)d_in[1];  // encoder_out [4096,16,512]
    const float* encf = (const float*)d_in[2];  // encoder_features [4096,16,512]
    const float* mask = (const float*)d_in[3];  // encoder_mask [16,1,4096]
    const float* tss  = (const float*)d_in[4];  // temporal_scores_sum [16,1,4096]
    const float* W    = (const float*)d_in[5];  // W_feat [512,512]
    const float* bias = (const float*)d_in[6];  // b_feat [512]
    const float* v    = (const float*)d_in[7];  // v_attn [512]

    float* out        = (float*)d_out;
    float* out_newsum = out + CTXN + BATCH * SEQ;  // third output

    k0_dec  <<<512,           256>>>(x, W, bias);
    kmain   <<<BATCH * SLOTS, 256>>>(encf, enc, mask, tss, v, out_newsum);
    k4_final<<<288,           256>>>(out);
}